// round 2
// baseline (speedup 1.0000x reference)
#include <cuda_runtime.h>

// VQ nearest-codebook quantization.
// Inputs:  d_in[0] = z_e_x  [65536, 128] fp32 (4096*16 rows)
//          d_in[1] = codebook [1024, 128] fp32
// Outputs (fp32, concatenated in reference return order):
//   codes      [65536*128]
//   flat_idx   [65536]   (as float)
//   idx        [65536]   (same values, reshape only)
//   distances  [65536]

#define BM 128
#define BN 128
#define BK 8
#define TM 8
#define TN 8
#define C_DIM 128

#define ROWS_MAX 65536
#define CODES_MAX 1024

__device__ float g_xsq[ROWS_MAX];
__device__ float g_csq[CODES_MAX];

// One warp per row: sum of squares of 128 floats.
__global__ void xsq_kernel(const float* __restrict__ X) {
    int row = blockIdx.x * blockDim.y + threadIdx.y;
    float4 v = reinterpret_cast<const float4*>(X + (size_t)row * C_DIM)[threadIdx.x];
    float s = v.x * v.x + v.y * v.y + v.z * v.z + v.w * v.w;
    #pragma unroll
    for (int o = 16; o; o >>= 1) s += __shfl_xor_sync(0xffffffffu, s, o);
    if (threadIdx.x == 0) g_xsq[row] = s;
}

__global__ void csq_kernel(const float* __restrict__ CB) {
    int row = blockIdx.x * blockDim.y + threadIdx.y;
    float4 v = reinterpret_cast<const float4*>(CB + (size_t)row * C_DIM)[threadIdx.x];
    float s = v.x * v.x + v.y * v.y + v.z * v.z + v.w * v.w;
    #pragma unroll
    for (int o = 16; o; o >>= 1) s += __shfl_xor_sync(0xffffffffu, s, o);
    if (threadIdx.x == 0) g_csq[row] = s;
}

// Main kernel: per 128-row block, scan all 1024 codes with a 128x128x8
// register-tiled fp32 GEMM, tracking per-row argmin of (csq - 2*dot).
__global__ __launch_bounds__(256, 2)
void vq_kernel(const float* __restrict__ X, const float* __restrict__ CB,
               float* __restrict__ out_codes,
               float* __restrict__ out_fidx,
               float* __restrict__ out_idx,
               float* __restrict__ out_dist,
               int n_codes)
{
    __shared__ float As[BK][BM];
    __shared__ float Bs[BK][BN];
    __shared__ float rv[BM][16];
    __shared__ int   ri[BM][16];

    const int tid = threadIdx.x;
    const int tx = tid & 15;        // column group 0..15
    const int ty = tid >> 4;        // row group 0..15
    const int block_row = blockIdx.x * BM;

    float bestv[TM];
    int   besti[TM];
    #pragma unroll
    for (int i = 0; i < TM; i++) { bestv[i] = 3.4e38f; besti[i] = 0; }

    const int lr  = tid >> 1;           // 0..127, row within tile for loads
    const int lc4 = (tid & 1) * 4;      // 0 or 4, starting k-col for loads

    const int n_ctiles = n_codes / BN;

    for (int ct = 0; ct < n_ctiles; ct++) {
        float acc[TM][TN];
        #pragma unroll
        for (int i = 0; i < TM; i++)
            #pragma unroll
            for (int j = 0; j < TN; j++) acc[i][j] = 0.0f;

        #pragma unroll 1
        for (int k0 = 0; k0 < C_DIM; k0 += BK) {
            // Load A tile (transposed): rows block_row..+127, cols k0..k0+7
            {
                float4 va = *reinterpret_cast<const float4*>(
                    X + (size_t)(block_row + lr) * C_DIM + k0 + lc4);
                As[lc4 + 0][lr] = va.x;
                As[lc4 + 1][lr] = va.y;
                As[lc4 + 2][lr] = va.z;
                As[lc4 + 3][lr] = va.w;
                float4 vb = *reinterpret_cast<const float4*>(
                    CB + (size_t)(ct * BN + lr) * C_DIM + k0 + lc4);
                Bs[lc4 + 0][lr] = vb.x;
                Bs[lc4 + 1][lr] = vb.y;
                Bs[lc4 + 2][lr] = vb.z;
                Bs[lc4 + 3][lr] = vb.w;
            }
            __syncthreads();

            #pragma unroll
            for (int kk = 0; kk < BK; kk++) {
                float4 a0 = *reinterpret_cast<const float4*>(&As[kk][ty * TM]);
                float4 a1 = *reinterpret_cast<const float4*>(&As[kk][ty * TM + 4]);
                float4 b0 = *reinterpret_cast<const float4*>(&Bs[kk][tx * TN]);
                float4 b1 = *reinterpret_cast<const float4*>(&Bs[kk][tx * TN + 4]);
                float a[TM] = {a0.x, a0.y, a0.z, a0.w, a1.x, a1.y, a1.z, a1.w};
                float b[TN] = {b0.x, b0.y, b0.z, b0.w, b1.x, b1.y, b1.z, b1.w};
                #pragma unroll
                for (int i = 0; i < TM; i++)
                    #pragma unroll
                    for (int j = 0; j < TN; j++)
                        acc[i][j] += a[i] * b[j];
            }
            __syncthreads();
        }

        // Fold: score = csq - 2*dot; track running min (strict < keeps
        // earliest index; j ascending and ct ascending preserve
        // first-occurrence argmin semantics within a thread).
        #pragma unroll
        for (int j = 0; j < TN; j++) {
            int code = ct * BN + tx * TN + j;
            float cs = g_csq[code];
            #pragma unroll
            for (int i = 0; i < TM; i++) {
                float v = fmaf(-2.0f, acc[i][j], cs);
                if (v < bestv[i]) { bestv[i] = v; besti[i] = code; }
            }
        }
    }

    // Cross-thread reduction: 16 tx-threads cover each row.
    #pragma unroll
    for (int i = 0; i < TM; i++) {
        rv[ty * TM + i][tx] = bestv[i];
        ri[ty * TM + i][tx] = besti[i];
    }
    __syncthreads();

    if (tid < BM) {
        float bv = rv[tid][0];
        int   bi = ri[tid][0];
        #pragma unroll
        for (int t = 1; t < 16; t++) {
            float v = rv[tid][t];
            int   ii = ri[tid][t];
            // explicit tie-break: first (smallest) index wins
            if (v < bv || (v == bv && ii < bi)) { bv = v; bi = ii; }
        }
        int row = block_row + tid;
        if (out_fidx) {
            float fbi = (float)bi;
            out_fidx[row] = fbi;
            out_idx[row]  = fbi;
            out_dist[row] = g_xsq[row] + bv;
        }
        ri[tid][0] = bi;   // stash winning code for the gather
    }
    __syncthreads();

    // Codes gather: 2 threads per row, 64 floats (16 float4) each.
    {
        int r = tid >> 1;
        int half = tid & 1;
        int code = ri[r][0];
        const float4* src = reinterpret_cast<const float4*>(CB + (size_t)code * C_DIM) + half * 16;
        float4* dst = reinterpret_cast<float4*>(out_codes + (size_t)(block_row + r) * C_DIM) + half * 16;
        #pragma unroll
        for (int q = 0; q < 16; q++) dst[q] = src[q];
    }
}

extern "C" void kernel_launch(void* const* d_in, const int* in_sizes, int n_in,
                              void* d_out, int out_size)
{
    const float* X  = (const float*)d_in[0];
    const float* CB = (const float*)d_in[1];
    float* out = (float*)d_out;

    const int n_rows  = in_sizes[0] / C_DIM;   // 65536
    const int n_codes = in_sizes[1] / C_DIM;   // 1024

    // Output layout (fp32): codes | flat_idx | idx | distances
    size_t codes_n = (size_t)n_rows * C_DIM;
    bool extras = ((size_t)out_size >= codes_n + 3 * (size_t)n_rows);

    float* out_codes = out;
    float* out_fidx  = extras ? out + codes_n : nullptr;
    float* out_idx   = extras ? out + codes_n + n_rows : nullptr;
    float* out_dist  = extras ? out + codes_n + 2 * (size_t)n_rows : nullptr;

    // Precompute row norms (warp per row).
    xsq_kernel<<<n_rows / 8, dim3(32, 8)>>>(X);
    csq_kernel<<<n_codes / 8, dim3(32, 8)>>>(CB);

    vq_kernel<<<n_rows / BM, 256>>>(X, CB, out_codes, out_fidx, out_idx,
                                    out_dist, n_codes);
}

// round 4
// speedup vs baseline: 2.3951x; 2.3951x over previous
#include <cuda_runtime.h>
#include <cuda_fp16.h>
#include <cstdint>

// VQ nearest-codebook quantization via warp-level mma.sync fp16-split GEMM.
// Inputs:  d_in[0] = z_e_x  [65536, 128] fp32,  d_in[1] = codebook [1024, 128] fp32
// Outputs (fp32): codes [65536*128] | flat_idx [65536] | idx [65536] | dist [65536]

#define C_DIM 128
#define BM    128

// ---- SMEM layout (bytes) ----
#define OFF_CSQ   0         // 1024 fp32 = 4096
#define OFF_XSQ   4096      // 128 fp32 = 512
#define OFF_REDV  4608      // 128*8 fp32 = 4096
#define OFF_REDI  8704      // 128*8 int  = 4096
#define OFF_A_H   16384     // 128x128 fp16 swizzled = 32768
#define OFF_A_L   49152     // 32768
#define OFF_B     81920     // 2 x 64KB (hi 32KB | lo 32KB)
#define B_BUF     65536
#define SMEM_TOTAL 212992

// Pre-split codebook, per-chunk SMEM image: [8 chunks][hi 32KB | lo 32KB]
__device__ uint4 g_B[8 * 4096];     // 512 KB
__device__ float g_csq[1024];

// ---------------- helpers ----------------
__device__ __forceinline__ uint32_t smem_u32(const void* p) {
    uint32_t a;
    asm("{ .reg .u64 t; cvta.to.shared.u64 t, %1; cvt.u32.u64 %0, t; }" : "=r"(a) : "l"(p));
    return a;
}
__device__ __forceinline__ void ldsm_x4(uint32_t* r, uint32_t addr) {
    asm volatile("ldmatrix.sync.aligned.m8n8.x4.shared.b16 {%0,%1,%2,%3}, [%4];"
                 : "=r"(r[0]), "=r"(r[1]), "=r"(r[2]), "=r"(r[3]) : "r"(addr));
}
__device__ __forceinline__ void mma16816(float* c, const uint32_t* a, const uint32_t* b) {
    asm volatile("mma.sync.aligned.m16n8k16.row.col.f32.f16.f16.f32 "
                 "{%0,%1,%2,%3}, {%4,%5,%6,%7}, {%8,%9}, {%0,%1,%2,%3};"
                 : "+f"(c[0]), "+f"(c[1]), "+f"(c[2]), "+f"(c[3])
                 : "r"(a[0]), "r"(a[1]), "r"(a[2]), "r"(a[3]), "r"(b[0]), "r"(b[1]));
}
#define CP_ASYNC16(dst, src) \
    asm volatile("cp.async.cg.shared.global [%0], [%1], 16;" :: "r"(dst), "l"(src))
#define CP_COMMIT() asm volatile("cp.async.commit_group;" ::: "memory")
#define CP_WAIT1()  asm volatile("cp.async.wait_group 1;" ::: "memory")

__device__ __forceinline__ void split2(float a, float b, uint32_t& hi, uint32_t& lo) {
    __half2 h = __floats2half2_rn(a, b);
    float2  f = __half22float2(h);
    __half2 l = __floats2half2_rn(a - f.x, b - f.y);
    hi = *reinterpret_cast<uint32_t*>(&h);
    lo = *reinterpret_cast<uint32_t*>(&l);
}

// ---------------- prep: split + swizzle codebook, csq ----------------
__global__ void prep_cb(const float* __restrict__ CB) {
    int t = blockIdx.x * blockDim.x + threadIdx.x;   // 0..2047
    int code = t >> 1, h = t & 1;
    const float4* src = reinterpret_cast<const float4*>(CB + (size_t)code * C_DIM + h * 64);
    char* base = (char*)g_B + (size_t)(code >> 7) * B_BUF;
    int r = code & 127;
    float s = 0.f;
    #pragma unroll
    for (int q = 0; q < 16; q += 2) {
        float4 v0 = src[q], v1 = src[q + 1];
        s += v0.x*v0.x + v0.y*v0.y + v0.z*v0.z + v0.w*v0.w
           + v1.x*v1.x + v1.y*v1.y + v1.z*v1.z + v1.w*v1.w;
        uint4 H, L;
        split2(v0.x, v0.y, H.x, L.x); split2(v0.z, v0.w, H.y, L.y);
        split2(v1.x, v1.y, H.z, L.z); split2(v1.z, v1.w, H.w, L.w);
        int cg = h * 8 + (q >> 1);                       // 16B chunk index 0..15
        uint32_t off = (uint32_t)(r * 256 + ((cg ^ (r & 7)) << 4));
        *reinterpret_cast<uint4*>(base + off) = H;           // hi at +0
        *reinterpret_cast<uint4*>(base + 32768 + off) = L;   // lo at +32KB
    }
    s += __shfl_xor_sync(0xffffffffu, s, 1);
    if (!h) g_csq[code] = s;
}

// ---------------- main kernel ----------------
__device__ __forceinline__ void issue_chunk(uint32_t sb, int buf, int chunk, int tid) {
    const char* src = (const char*)g_B + (size_t)chunk * B_BUF + tid * 16;
    uint32_t dst = sb + OFF_B + buf * B_BUF + tid * 16;
    #pragma unroll
    for (int i = 0; i < 16; i++)
        CP_ASYNC16(dst + i * 4096, src + i * 4096);
}

__global__ __launch_bounds__(256, 1)
void vq_main(const float* __restrict__ X, const float* __restrict__ CB,
             float* __restrict__ out_codes, float* __restrict__ out_fidx,
             float* __restrict__ out_idx,   float* __restrict__ out_dist,
             int n_codes)
{
    extern __shared__ char smem[];
    const uint32_t sb = smem_u32(smem);
    const int tid = threadIdx.x, lane = tid & 31, wid = tid >> 5;
    const int warpM = wid >> 1, warpN = wid & 1;
    const int block_row = blockIdx.x * BM;
    const int NC = n_codes >> 7;    // chunks of 128 codes

    issue_chunk(sb, 0, 0, tid);
    CP_COMMIT();

    // csq -> SMEM
    for (int i = tid; i < n_codes; i += 256)
        reinterpret_cast<float*>(smem + OFF_CSQ)[i] = g_csq[i];

    // A tile: fp32 rows -> fp16 hi/lo, swizzled; fused xsq.
    {
        const int r = tid >> 1, h = tid & 1;
        const float4* src = reinterpret_cast<const float4*>(
            X + (size_t)(block_row + r) * C_DIM + h * 64);
        float s = 0.f;
        #pragma unroll
        for (int q = 0; q < 16; q += 2) {
            float4 v0 = src[q], v1 = src[q + 1];
            s += v0.x*v0.x + v0.y*v0.y + v0.z*v0.z + v0.w*v0.w
               + v1.x*v1.x + v1.y*v1.y + v1.z*v1.z + v1.w*v1.w;
            uint4 H, L;
            split2(v0.x, v0.y, H.x, L.x); split2(v0.z, v0.w, H.y, L.y);
            split2(v1.x, v1.y, H.z, L.z); split2(v1.z, v1.w, H.w, L.w);
            int cg = h * 8 + (q >> 1);
            uint32_t off = (uint32_t)(r * 256 + ((cg ^ (r & 7)) << 4));
            *reinterpret_cast<uint4*>(smem + OFF_A_H + off) = H;
            *reinterpret_cast<uint4*>(smem + OFF_A_L + off) = L;
        }
        s += __shfl_xor_sync(0xffffffffu, s, 1);
        if (!h) reinterpret_cast<float*>(smem + OFF_XSQ)[r] = s;
    }

    if (NC > 1) issue_chunk(sb, 1, 1, tid);
    CP_COMMIT();
    __syncthreads();

    // per-thread ldmatrix address constants
    const uint32_t aOff   = (uint32_t)((warpM * 32 + (lane & 15)) * 256);
    const uint32_t bOff   = (uint32_t)((warpN * 64 + (lane & 7) + ((lane >> 4) << 3)) * 256);
    const uint32_t sw     = (uint32_t)(lane & 7);
    const uint32_t achsel = (uint32_t)(lane >> 4);
    const uint32_t bchsel = (uint32_t)((lane >> 3) & 1);

    float bestv[4];
    int   besti[4];
    #pragma unroll
    for (int i = 0; i < 4; i++) { bestv[i] = 3.4e38f; besti[i] = 0; }

    for (int c = 0; c < NC; c++) {
        CP_WAIT1();
        __syncthreads();

        const int buf = c & 1;
        float acc[2][8][4];
        #pragma unroll
        for (int mi = 0; mi < 2; mi++)
            #pragma unroll
            for (int ni = 0; ni < 8; ni++)
                #pragma unroll
                for (int j = 0; j < 4; j++) acc[mi][ni][j] = 0.f;

        #pragma unroll
        for (int pass = 0; pass < 3; pass++) {
            const uint32_t Ab = sb + (pass == 2 ? OFF_A_L : OFF_A_H) + aOff;
            const uint32_t Bb = sb + OFF_B + buf * B_BUF + (pass == 1 ? 32768 : 0) + bOff;
            #pragma unroll
            for (int ks = 0; ks < 8; ks++) {
                const uint32_t ach = (((uint32_t)(2 * ks) + achsel) ^ sw) << 4;
                const uint32_t bch = (((uint32_t)(2 * ks) + bchsel) ^ sw) << 4;
                uint32_t a[2][4], b[4][4];
                ldsm_x4(a[0], Ab + ach);
                ldsm_x4(a[1], Ab + 4096 + ach);
                #pragma unroll
                for (int nf2 = 0; nf2 < 4; nf2++)
                    ldsm_x4(b[nf2], Bb + nf2 * 4096 + bch);
                #pragma unroll
                for (int mi = 0; mi < 2; mi++)
                    #pragma unroll
                    for (int ni = 0; ni < 8; ni++)
                        mma16816(acc[mi][ni], a[mi], &b[ni >> 1][(ni & 1) * 2]);
            }
        }

        // fold: argmin of csq - 2*dot (strict <, ascending cols -> first-index)
        {
            const float* csqs = reinterpret_cast<const float*>(smem + OFF_CSQ)
                                + c * 128 + warpN * 64;
            #pragma unroll
            for (int mi = 0; mi < 2; mi++) {
                #pragma unroll
                for (int ni = 0; ni < 8; ni++) {
                    const int col = ni * 8 + (lane & 3) * 2;
                    const float cs0 = csqs[col], cs1 = csqs[col + 1];
                    const int gcol = c * 128 + warpN * 64 + col;
                    float v0 = fmaf(-2.f, acc[mi][ni][0], cs0);
                    float v1 = fmaf(-2.f, acc[mi][ni][1], cs1);
                    float v2 = fmaf(-2.f, acc[mi][ni][2], cs0);
                    float v3 = fmaf(-2.f, acc[mi][ni][3], cs1);
                    const int p0 = mi * 2, p1 = mi * 2 + 1;
                    if (v0 < bestv[p0]) { bestv[p0] = v0; besti[p0] = gcol; }
                    if (v1 < bestv[p0]) { bestv[p0] = v1; besti[p0] = gcol + 1; }
                    if (v2 < bestv[p1]) { bestv[p1] = v2; besti[p1] = gcol; }
                    if (v3 < bestv[p1]) { bestv[p1] = v3; besti[p1] = gcol + 1; }
                }
            }
        }

        __syncthreads();
        if (c + 2 < NC) issue_chunk(sb, buf, c + 2, tid);
        CP_COMMIT();                 // commit even when empty: keeps group count aligned
    }

    // write per-thread winners: rows x 8 slots
    #pragma unroll
    for (int mi = 0; mi < 2; mi++)
        #pragma unroll
        for (int rh = 0; rh < 2; rh++) {
            const int rowl = warpM * 32 + mi * 16 + rh * 8 + (lane >> 2);
            const int slot = warpN * 4 + (lane & 3);
            reinterpret_cast<float*>(smem + OFF_REDV)[rowl * 8 + slot] = bestv[mi * 2 + rh];
            reinterpret_cast<int*>(smem + OFF_REDI)[rowl * 8 + slot]   = besti[mi * 2 + rh];
        }
    __syncthreads();

    if (tid < BM) {
        const float* rv = reinterpret_cast<const float*>(smem + OFF_REDV) + tid * 8;
        const int*   ri = reinterpret_cast<const int*>(smem + OFF_REDI) + tid * 8;
        float bv = rv[0]; int bi = ri[0];
        #pragma unroll
        for (int s = 1; s < 8; s++) {
            float v = rv[s]; int ii = ri[s];
            if (v < bv || (v == bv && ii < bi)) { bv = v; bi = ii; }
        }
        const int row = block_row + tid;
        if (out_fidx) {
            float fbi = (float)bi;
            out_fidx[row] = fbi;
            out_idx[row]  = fbi;
            out_dist[row] = reinterpret_cast<float*>(smem + OFF_XSQ)[tid] + bv;
        }
        reinterpret_cast<int*>(smem + OFF_REDI)[tid * 8] = bi;  // stash for gather
    }
    __syncthreads();

    // codes gather: 2 threads per row, 64 floats each
    {
        const int r = tid >> 1, hh = tid & 1;
        const int code = reinterpret_cast<int*>(smem + OFF_REDI)[r * 8];
        const float4* src = reinterpret_cast<const float4*>(CB + (size_t)code * C_DIM) + hh * 16;
        float4* dst = reinterpret_cast<float4*>(out_codes + (size_t)(block_row + r) * C_DIM) + hh * 16;
        #pragma unroll
        for (int q = 0; q < 16; q++) dst[q] = src[q];
    }
}

extern "C" void kernel_launch(void* const* d_in, const int* in_sizes, int n_in,
                              void* d_out, int out_size)
{
    const float* X  = (const float*)d_in[0];
    const float* CB = (const float*)d_in[1];
    float* out = (float*)d_out;

    const int n_rows  = in_sizes[0] / C_DIM;   // 65536
    const int n_codes = in_sizes[1] / C_DIM;   // 1024

    size_t codes_n = (size_t)n_rows * C_DIM;
    bool extras = ((size_t)out_size >= codes_n + 3 * (size_t)n_rows);

    float* out_codes = out;
    float* out_fidx  = extras ? out + codes_n : nullptr;
    float* out_idx   = extras ? out + codes_n + n_rows : nullptr;
    float* out_dist  = extras ? out + codes_n + 2 * (size_t)n_rows : nullptr;

    static bool attr_set = false;
    if (!attr_set) {
        cudaFuncSetAttribute(vq_main, cudaFuncAttributeMaxDynamicSharedMemorySize, SMEM_TOTAL);
        attr_set = true;
    }

    prep_cb<<<(n_codes * 2) / 256, 256>>>(CB);
    vq_main<<<n_rows / BM, 256, SMEM_TOTAL>>>(X, CB, out_codes, out_fidx,
                                              out_idx, out_dist, n_codes);
}